// round 17
// baseline (speedup 1.0000x reference)
#include <cuda_runtime.h>
#include <cstdint>
#include <cmath>

#define T_SEQ   4096
#define TAGS    24
#define START_T 22
#define STOP_T  23
#define NEGV    (-10000.0f)

#define NCTA_DIR    64
#define REC_THREADS 288   // 8 compute warps + 1 publisher warp

// ---------------- scratch (device globals; no cudaMalloc allowed) ----------
__device__ float    g_lstm[(size_t)T_SEQ * 1024]; // [t][dir*512 + cell]
__device__ float    g_feats[T_SEQ * TAGS];
// h exchange: one 8B word per cell = (tag<<32 | fp32 bits). Tag==s+1 for the h
// that is INPUT to step s; double-buffered by step parity.
// Polls are ld.relaxed.gpu (morally strong: atomic, coherent, but unordered so
// the two per-lane polls overlap); publishes are st.release.gpu. R12's failure
// was WEAK (.cg) accesses — relaxed atomics do not have that problem.
__device__ unsigned long long g_hx[2][2][512];    // [dir][parity][cell]

__device__ __forceinline__ unsigned long long ld_rlx64(const unsigned long long* p)
{
    unsigned long long v;
    asm volatile("ld.relaxed.gpu.global.u64 %0, [%1];" : "=l"(v) : "l"(p) : "memory");
    return v;
}
__device__ __forceinline__ void st_rel64(unsigned long long* p, unsigned long long v)
{
    asm volatile("st.release.gpu.global.u64 [%0], %1;" :: "l"(p), "l"(v) : "memory");
}
__device__ __forceinline__ void fence_acq()
{
    asm volatile("fence.acq_rel.gpu;" ::: "memory");
}
__device__ __forceinline__ unsigned long long pack_ht(float h, unsigned tag)
{
    return ((unsigned long long)tag << 32) | (unsigned long long)__float_as_uint(h);
}

#define FMA2(d, a, b, c) \
    asm("fma.rn.f32x2 %0, %1, %2, %3;" : "=l"(d) : "l"(a), "l"(b), "l"(c))

// producer/consumer named barrier (id 1, all 288 threads)
#define BAR_ARRIVE() asm volatile("bar.arrive 1, 288;" ::: "memory")
#define BAR_SYNC()   asm volatile("bar.sync   1, 288;" ::: "memory")

// ---------------- kernel 1: persistent BiLSTM recurrence (x-proj fused) ----
// 128 CTAs (64/dir), 288 threads. Warps 0-7 (w = k-slice [64w,64w+64), lane l
// = gate-row): stage emb -> issue relaxed polls -> x-dot (overlaps poll RTT)
// -> emb prefetch -> poll finish -> h-dot -> sg[parity] -> bar.arrive -> next.
// Warp 8 (publisher only): bar.sync -> reduce+bias -> parallel activations ->
// cst update -> st.release publish. Publish is on NO compute path.
__global__ void __launch_bounds__(REC_THREADS, 1)
lstm_rec(const float* __restrict__ whf, const float* __restrict__ whb,
         const float* __restrict__ wif, const float* __restrict__ wib,
         const float* __restrict__ bihf, const float* __restrict__ bhhf,
         const float* __restrict__ bihb, const float* __restrict__ bhhb,
         const float* __restrict__ h0, const float* __restrict__ c0,
         const int* __restrict__ sent, const float* __restrict__ emb)
{
    const int cta = blockIdx.x;       // 0..127
    const int d   = cta >> 6;
    const int r   = cta & 63;         // owns cells [8r, 8r+8)
    const int tid = threadIdx.x;
    const int w   = tid >> 5;         // 0..8 (8 = publisher)
    const int l   = tid & 31;
    const int gate = l >> 3;
    const int cell = (r << 3) + (l & 7);
    const int row  = gate * 512 + cell;

    __shared__ __align__(16) float  hsh[8][64];   // per-warp staged h slice
    __shared__ __align__(16) float4 xsm[8][16];   // per-warp staged emb slice
    __shared__ float sg[2][8][33];                // parity-buffered partials

    if (w < 8) {
        // ================= compute warps =================
        const float* whh = d ? whb : whf;
        const float* wih = d ? wib : wif;

        unsigned long long W2[32], WX2[32];
        {
            const float2* wp = (const float2*)(whh + (size_t)row * 512 + (w << 6));
            const float2* xp = (const float2*)(wih + (size_t)row * 512 + (w << 6));
#pragma unroll
            for (int i = 0; i < 32; i++) {
                float2 v = wp[i];
                W2[i] = ((unsigned long long)__float_as_uint(v.y) << 32)
                      | (unsigned long long)__float_as_uint(v.x);
                float2 u = xp[i];
                WX2[i] = ((unsigned long long)__float_as_uint(u.y) << 32)
                       | (unsigned long long)__float_as_uint(u.x);
            }
        }

        // prefetch emb row for step 0
        float4 xf = {0.f, 0.f, 0.f, 0.f};
        {
            int t0 = d ? (T_SEQ - 1) : 0;
            int tok = __ldg(&sent[t0]);
            if (l < 16)
                xf = __ldg((const float4*)(emb + (size_t)tok * 512 + (w << 6)) + l);
        }

        for (int s = 0; s < T_SEQ; s++) {
            // ---- stage prefetched emb slice ----
            if (l < 16) xsm[w][l] = xf;
            __syncwarp();

            // ---- issue relaxed poll loads EARLY (they overlap each other
            //      AND the x-dot below) ----
            const unsigned want = (unsigned)(s + 1);
            const unsigned long long* hb = &g_hx[d][s & 1][w << 6];
            unsigned long long v0 = ld_rlx64(hb + l);
            unsigned long long v1 = ld_rlx64(hb + 32 + l);

            // ---- x-dot (independent of h) ----
            const ulonglong2* xv2 = (const ulonglong2*)&xsm[w][0];
            unsigned long long ax0 = 0ull, ax1 = 0ull;
#pragma unroll
            for (int i = 0; i < 16; i++) {
                ulonglong2 x2 = xv2[i];
                FMA2(ax0, WX2[2 * i],     x2.x, ax0);
                FMA2(ax1, WX2[2 * i + 1], x2.y, ax1);
            }

            // ---- prefetch next step's emb row (hidden behind poll) ----
            if (s + 1 < T_SEQ) {
                int tn  = d ? (T_SEQ - 2 - s) : (s + 1);
                int tok = __ldg(&sent[tn]);
                if (l < 16)
                    xf = __ldg((const float4*)(emb + (size_t)tok * 512 + (w << 6)) + l);
            }

            // ---- finish poll (relaxed iterations overlap; acquire fence
            //      once on exit) ----
            {
                bool d0 = ((unsigned)(v0 >> 32) == want);
                bool d1 = ((unsigned)(v1 >> 32) == want);
                while (!__all_sync(0xffffffffu, d0 && d1)) {
                    if (!d0) { v0 = ld_rlx64(hb + l);      d0 = ((unsigned)(v0 >> 32) == want); }
                    if (!d1) { v1 = ld_rlx64(hb + 32 + l); d1 = ((unsigned)(v1 >> 32) == want); }
                }
                fence_acq();
                hsh[w][l]      = __uint_as_float((unsigned)v0);
                hsh[w][32 + l] = __uint_as_float((unsigned)v1);
            }
            __syncwarp();

            // ---- h-dot ----
            const ulonglong2* hv = (const ulonglong2*)&hsh[w][0];
            unsigned long long a0 = 0ull, a1 = 0ull;
#pragma unroll
            for (int i = 0; i < 16; i++) {
                ulonglong2 h2 = hv[i];
                FMA2(a0, W2[2 * i],     h2.x, a0);
                FMA2(a1, W2[2 * i + 1], h2.y, a1);
            }
            float ph = (__uint_as_float((unsigned)a0) + __uint_as_float((unsigned)(a0 >> 32)))
                     + (__uint_as_float((unsigned)a1) + __uint_as_float((unsigned)(a1 >> 32)));
            float px = (__uint_as_float((unsigned)ax0) + __uint_as_float((unsigned)(ax0 >> 32)))
                     + (__uint_as_float((unsigned)ax1) + __uint_as_float((unsigned)(ax1 >> 32)));
            sg[s & 1][w][l] = ph + px;
            // signal publisher; race ahead. sg WAR safe: rewriting sg[s&1] at
            // s+2 needs own warp8's tag s+3 (published at s+1), i.e. warp8
            // already consumed sg[s&1] at step s.
            BAR_ARRIVE();
        }
    } else {
        // ================= publisher warp (warp 8) =================
        const float bias = d ? (bihb[row] + bhhb[row]) : (bihf[row] + bhhf[row]);

        float cst = 0.f;
        if (l < 8) {
            cst = c0[d * 512 + (r << 3) + l];
            st_rel64(&g_hx[d][0][(r << 3) + l],
                     pack_ht(h0[d * 512 + (r << 3) + l], 1u));
        }

        for (int s = 0; s < T_SEQ; s++) {
            const int t = d ? (T_SEQ - 1 - s) : s;
            BAR_SYNC();   // wait for the 8 partials of step s
            const float (*sgp)[33] = sg[s & 1];
            float a = ((sgp[0][l] + sgp[1][l]) + (sgp[2][l] + sgp[3][l]))
                    + ((sgp[4][l] + sgp[5][l]) + (sgp[6][l] + sgp[7][l]));
            a += bias;
            // parallel activations (bit-identical to serial form)
            float act = (gate == 2) ? tanhf(a) : (1.f / (1.f + expf(-a)));
            float fg = __shfl_sync(0xffffffffu, act, (l & 7) + 8);
            float gg = __shfl_sync(0xffffffffu, act, (l & 7) + 16);
            float ov = __shfl_sync(0xffffffffu, act, (l & 7) + 24);
            if (l < 8) {
                cst = fg * cst + act * gg;          // act = sigmoid(i) here
                float hn = ov * tanhf(cst);
                st_rel64(&g_hx[d][(s + 1) & 1][(r << 3) + l],
                         pack_ht(hn, (unsigned)(s + 2)));
                __stcg(&g_lstm[(size_t)t * 1024 + d * 512 + (r << 3) + l], hn);
            }
        }
    }
}

// ---------------- kernel 2: tag features -----------------------------------
__global__ void feats_k(const float* __restrict__ wtag, const float* __restrict__ btag)
{
    const int t = blockIdx.x;
    const int w = threadIdx.x >> 5;
    const int lane = threadIdx.x & 31;

    const float4* lx = (const float4*)(g_lstm + (size_t)t * 1024 + lane * 32);
    float4 X[8];
#pragma unroll
    for (int i = 0; i < 8; i++) X[i] = lx[i];

#pragma unroll
    for (int rep = 0; rep < 3; rep++) {
        int tag = w + rep * 8;
        const float4* wt = (const float4*)(wtag + (size_t)tag * 1024 + lane * 32);
        float a = 0.f;
#pragma unroll
        for (int i = 0; i < 8; i++) {
            float4 v = wt[i];
            a += X[i].x * v.x + X[i].y * v.y + X[i].z * v.z + X[i].w * v.w;
        }
#pragma unroll
        for (int o = 16; o; o >>= 1) a += __shfl_xor_sync(0xffffffffu, a, o);
        if (lane == 0) g_feats[t * TAGS + tag] = a + btag[tag];
    }
}

// ---------------- kernel 3: Viterbi (1 warp, bp in smem) -------------------
__global__ void viterbi_k(const float* __restrict__ trans, float* __restrict__ out,
                          int out_size)
{
    extern __shared__ unsigned char bp[];      // T_SEQ * TAGS bytes
    __shared__ float trs[TAGS * 25];
    __shared__ float stopr[TAGS];

    const int lane = threadIdx.x;
    for (int i = lane; i < TAGS * TAGS; i += 32) {
        int n = i / TAGS, p = i % TAGS;
        trs[n * 25 + p] = trans[i];
    }
    if (lane < TAGS) stopr[lane] = trans[STOP_T * TAGS + lane];
    __syncwarp();

    float fv = (lane == START_T) ? 0.f : NEGV;
    float feat = (lane < TAGS) ? g_feats[lane] : 0.f;

    for (int t = 0; t < T_SEQ; t++) {
        float nf = (lane < TAGS && t + 1 < T_SEQ) ? g_feats[(t + 1) * TAGS + lane] : 0.f;
        float best = -3.4e38f;
        int bi = 0;
#pragma unroll
        for (int p = 0; p < TAGS; p++) {
            float src = __shfl_sync(0xffffffffu, fv, p);
            float v = src + ((lane < TAGS) ? trs[lane * 25 + p] : 0.f);
            if (v > best) { best = v; bi = p; }
        }
        if (lane < TAGS) {
            fv = best + feat;
            bp[t * TAGS + lane] = (unsigned char)bi;
        } else {
            fv = NEGV;
        }
        feat = nf;
    }

    float ttl = (lane < TAGS) ? fv + stopr[lane] : -3.4e38f;
    float bv = ttl; int bi = lane;
#pragma unroll
    for (int o = 16; o; o >>= 1) {
        float ov = __shfl_down_sync(0xffffffffu, bv, o);
        int   oi = __shfl_down_sync(0xffffffffu, bi, o);
        if (ov > bv || (ov == bv && oi < bi)) { bv = ov; bi = oi; }
    }

    if (lane == 0) {
        float score = bv;
        int cur = bi;
        if (out_size >= T_SEQ + 1) {
            out[0] = score;
            float* path = out + 1;
            path[T_SEQ - 1] = (float)cur;
            for (int t = T_SEQ - 1; t >= 1; t--) {
                cur = bp[t * TAGS + cur];
                path[t - 1] = (float)cur;
            }
        } else if (out_size == T_SEQ) {
            out[T_SEQ - 1] = (float)cur;
            for (int t = T_SEQ - 1; t >= 1; t--) {
                cur = bp[t * TAGS + cur];
                out[t - 1] = (float)cur;
            }
        } else {
            out[0] = score;
        }
    }
}

// ---------------- launcher --------------------------------------------------
extern "C" void kernel_launch(void* const* d_in, const int* in_sizes, int n_in,
                              void* d_out, int out_size)
{
    const int*   sent  = (const int*)  d_in[0];
    const float* emb   = (const float*)d_in[1];
    const float* wihf  = (const float*)d_in[2];
    const float* whhf  = (const float*)d_in[3];
    const float* bihf  = (const float*)d_in[4];
    const float* bhhf  = (const float*)d_in[5];
    const float* wihb  = (const float*)d_in[6];
    const float* whhb  = (const float*)d_in[7];
    const float* bihb  = (const float*)d_in[8];
    const float* bhhb  = (const float*)d_in[9];
    const float* wtag  = (const float*)d_in[10];
    const float* btag  = (const float*)d_in[11];
    const float* trans = (const float*)d_in[12];
    const float* h0    = (const float*)d_in[13];
    const float* c0    = (const float*)d_in[14];
    float* out = (float*)d_out;

    lstm_rec<<<2 * NCTA_DIR, REC_THREADS>>>(whhf, whhb, wihf, wihb,
                                            bihf, bhhf, bihb, bhhb,
                                            h0, c0, sent, emb);
    feats_k<<<T_SEQ, 256>>>(wtag, btag);

    cudaFuncSetAttribute(viterbi_k, cudaFuncAttributeMaxDynamicSharedMemorySize,
                         T_SEQ * TAGS);
    viterbi_k<<<1, 32, T_SEQ * TAGS>>>(trans, out, out_size);
}